// round 7
// baseline (speedup 1.0000x reference)
#include <cuda_runtime.h>
#include <cuda_bf16.h>
#include <cuda_fp16.h>
#include <cstdint>

// Problem constants
#define Nn   400000
#define Hh   256
#define Cc   128
#define Aa   32
#define Gg   512
#define NGg  1024
#define CpA  (Cc + Aa)          // 160
#define BN_EPS 1e-5f

#define Kt   512                // concat K: [init | fin]
#define Nt   256                // outputs: [gate(128) | t(128)]
#define Mt   128                // nodes per block
#define KC   64                 // K chunk
#define AROW (KC + 8)           // padded smem row, elems (72)
#define NTHR 256                // 8 warps: 2 row-groups x 4 col-groups (64x64 tiles)

// ---------------- scratch (no allocations allowed) ----------------
__device__ float g_readout[NGg * Cc];            // segment sums  [1024,128]
__device__ float g_scale[CpA];
__device__ float g_shift[CpA];
__device__ float g_hidden[NGg * Gg];
__device__ __align__(16) __half g_Bh[Nt * Kt];   // combined weights [n][k], fp16

// ---------------- PTX helpers ----------------
__device__ __forceinline__ uint32_t smem_u32(const void* p) {
    uint32_t a;
    asm("{ .reg .u64 t; cvta.to.shared.u64 t, %1; cvt.u32.u64 %0, t; }" : "=r"(a) : "l"(p));
    return a;
}
#define LDSM4(r, addr)                                                        \
    asm volatile("ldmatrix.sync.aligned.m8n8.x4.shared.b16 {%0,%1,%2,%3}, [%4];" \
        : "=r"((r)[0]), "=r"((r)[1]), "=r"((r)[2]), "=r"((r)[3]) : "r"(addr))

#define MMA(d, a, b0, b1)                                                     \
    asm volatile("mma.sync.aligned.m16n8k16.row.col.f32.f16.f16.f32 "         \
        "{%0,%1,%2,%3},{%4,%5,%6,%7},{%8,%9},{%0,%1,%2,%3};"                  \
        : "+f"((d)[0]), "+f"((d)[1]), "+f"((d)[2]), "+f"((d)[3])              \
        : "r"((a)[0]), "r"((a)[1]), "r"((a)[2]), "r"((a)[3]), "r"(b0), "r"(b1))

#define CP16(dst, src)                                                        \
    asm volatile("cp.async.cg.shared.global [%0], [%1], 16;" :: "r"(dst), "l"(src) : "memory")
#define CP_COMMIT() asm volatile("cp.async.commit_group;" ::: "memory")
#define CP_WAIT0()  asm volatile("cp.async.wait_group 0;" ::: "memory")
#define CP_WAIT1()  asm volatile("cp.async.wait_group 1;" ::: "memory")

// ---------------- packed f32x2 helpers (MLP tail kernels) ----------------
__device__ __forceinline__ unsigned long long pack2(float lo, float hi) {
    unsigned long long r;
    asm("mov.b64 %0, {%1, %2};" : "=l"(r) : "f"(lo), "f"(hi));
    return r;
}
__device__ __forceinline__ void unpack2(unsigned long long v, float& lo, float& hi) {
    asm("mov.b64 {%0, %1}, %2;" : "=f"(lo), "=f"(hi) : "l"(v));
}
__device__ __forceinline__ unsigned long long fma2(unsigned long long a,
                                                   unsigned long long b,
                                                   unsigned long long c) {
    unsigned long long d;
    asm("fma.rn.f32x2 %0, %1, %2, %3;" : "=l"(d) : "l"(a), "l"(b), "l"(c));
    return d;
}

// ---------------- kernel: build combined fp16 weights + zero readout ----------------
// B[n][k]: n<128 -> Wg[k][n]; n>=128 -> (k>=256 ? Wt[k-256][n-128] : 0)
__global__ void prep_kernel(const float* __restrict__ Wg, const float* __restrict__ Wt) {
    int idx = blockIdx.x * 256 + threadIdx.x;     // 0 .. 131071
    int n = idx >> 9, k = idx & 511;
    float w;
    if (n < 128)          w = Wg[(size_t)k * Cc + n];
    else if (k >= 256)    w = Wt[(size_t)(k - 256) * Cc + (n - 128)];
    else                  w = 0.0f;
    g_Bh[idx] = __float2half_rn(w);
    g_readout[idx] = 0.0f;
}

// ---------------- node kernel: HMMA GEMM + gate + segment-sum ----------------
// dynamic smem, 4 stages of:
//   A [128][72] fp16 (18432B) | B [256][72] fp16 (36864B)   = 55296B/stage
#define OFF_B     18432
#define STG       55296
#define SMEM_DYN  (4 * STG)      // 221184
#define OUTROW    132            // fp32 out tile row stride (elems)

__device__ __forceinline__ void ldgA(const float* __restrict__ X, int nodeBase,
                                     int kloc, int tid, float4* aR) {
#pragma unroll
    for (int it = 0; it < 8; ++it) {
        int f = tid + it * NTHR;
        int m = f >> 4, q = f & 15;
        aR[it] = *(const float4*)(X + (size_t)(nodeBase + m) * Hh + kloc + 4 * q);
    }
}

__device__ __forceinline__ void stsA(char* stage, int tid, const float4* aR) {
#pragma unroll
    for (int it = 0; it < 8; ++it) {
        int f = tid + it * NTHR;
        int m = f >> 4, q = f & 15;
        float4 v = aR[it];
        __half2 h0 = __floats2half2_rn(v.x, v.y);
        __half2 h1 = __floats2half2_rn(v.z, v.w);
        uint32_t off = m * (AROW * 2) + q * 8;
        uint2 H; H.x = *(uint32_t*)&h0; H.y = *(uint32_t*)&h1;
        *(uint2*)(stage + off) = H;
    }
}

// copy B rows [0, nrows) for one K chunk; nrows is 128 (gate-only) or 256
__device__ __forceinline__ void cpB(uint32_t stB, int kbytes, int tid, int nrows) {
    const int iters = nrows >> 5;                // 4 or 8
    for (int it = 0; it < iters; ++it) {
        int f = tid + it * NTHR;
        int n = f >> 3, q = f & 7;
        uint32_t dst = n * (AROW * 2) + q * 16;
        CP16(stB + dst, (const char*)g_Bh + (size_t)n * (Kt * 2) + kbytes + q * 16);
    }
    CP_COMMIT();
}

__global__ __launch_bounds__(NTHR, 1)
void node_kernel(const float* __restrict__ xinit, const float* __restrict__ xfin,
                 const int* __restrict__ gids,
                 const float* __restrict__ bg, const float* __restrict__ bt) {
    extern __shared__ char smem[];
    __shared__ int s_gid[Mt];
    const uint32_t sbase = smem_u32(smem);
    const int tid = threadIdx.x;
    const int wid = tid >> 5;
    const int l = tid & 31;
    const int wm = wid & 1;          // 0..1 -> 64 rows each
    const int wn = wid >> 1;         // 0..3 -> 64 cols each
    const int nodeBase = blockIdx.x * Mt;

    if (tid < Mt) s_gid[tid] = gids[nodeBase + tid];

    // ldmatrix per-thread offsets (bytes)
    const uint32_t aOff = ((wm * 64 + (l & 15)) * AROW + ((l >> 4) * 8)) * 2;
    const uint32_t bOff = ((wn * 64 + ((l >> 4) & 1) * 8 + (l & 7)) * AROW +
                           ((l >> 3) & 1) * 8) * 2 + OFF_B;

    float acc[4][8][4];              // [mt 16-row][nt 8-col][frag]
#pragma unroll
    for (int i = 0; i < 4; i++)
#pragma unroll
        for (int j = 0; j < 8; j++)
#pragma unroll
            for (int p = 0; p < 4; p++) acc[i][j][p] = 0.0f;

    float4 rA[8];

    // prologue: chunks 0,1 staged; B 0,1 in flight
    ldgA(xinit, nodeBase, 0, tid, rA);
    cpB(sbase + OFF_B, 0, tid, 128);                 // group g0
    stsA(smem, tid, rA);
    ldgA(xinit, nodeBase, KC, tid, rA);
    cpB(sbase + STG + OFF_B, KC * 2, tid, 128);      // group g1
    stsA(smem + STG, tid, rA);
    CP_WAIT1();                                      // g0 done
    __syncthreads();

    for (int j = 0; j < 8; ++j) {
        const uint32_t stg = sbase + (uint32_t)(j & 3) * STG;
        // B for chunk j+2 (2 ahead) and LDG A chunk j+2
        if (j + 2 < 8) {
            const int c = j + 2;
            cpB(sbase + (uint32_t)(c & 3) * STG + OFF_B, c * KC * 2, tid,
                (c < 4) ? 128 : 256);
            const float* X = (c < 4) ? xinit : xfin;
            ldgA(X, nodeBase, (c & 3) * KC, tid, rA);
        }

        // chunks 0-3 hit the init half, where all t-columns of B are zero:
        // t warps (wn >= 2) skip their LDSM+MMA block entirely.
        if (j >= 4 || wn < 2) {
#pragma unroll
            for (int ks = 0; ks < 4; ++ks) {
                const uint32_t aA = stg + aOff + ks * 32;
                uint32_t ah[4][4];
#pragma unroll
                for (int mt = 0; mt < 4; ++mt)
                    LDSM4(ah[mt], aA + mt * (16 * AROW * 2));
#pragma unroll
                for (int np = 0; np < 4; ++np) {
                    const uint32_t bA = stg + bOff + np * (16 * AROW * 2) + ks * 32;
                    uint32_t bh[4];
                    LDSM4(bh, bA);
#pragma unroll
                    for (int mt = 0; mt < 4; ++mt) {
                        MMA(acc[mt][2 * np],     ah[mt], bh[0], bh[1]);
                        MMA(acc[mt][2 * np + 1], ah[mt], bh[2], bh[3]);
                    }
                }
            }
        }

        // STS chunk j+2 (LDG'd at top of this iteration -> one MMA block of slack)
        if (j + 2 < 8) stsA(smem + ((j + 2) & 3) * STG, tid, rA);
        // guarantee B group for chunk j+1 has landed before next iter consumes it
        if (j + 2 < 8)      CP_WAIT1();
        else if (j + 1 < 8) CP_WAIT0();
        __syncthreads();
    }

    // ---- epilogue ----
    float* sOut = (float*)smem;          // [128][OUTROW] fp32, aliases stages
    const int r = l >> 2;
    const int cq = (l & 3) * 2;

    if (wn < 2) {        // gate warps: store raw gate logits
#pragma unroll
        for (int mt = 0; mt < 4; ++mt)
#pragma unroll
            for (int nt = 0; nt < 8; ++nt) {
                int m = wm * 64 + mt * 16 + r;
                int c = wn * 64 + nt * 8 + cq;
                float* p = sOut + m * OUTROW + c;
                p[0] = acc[mt][nt][0];
                p[1] = acc[mt][nt][1];
                p[8 * OUTROW] = acc[mt][nt][2];
                p[8 * OUTROW + 1] = acc[mt][nt][3];
            }
    }
    __syncthreads();
    if (wn >= 2) {       // t warps: out = sigmoid(g + bg) * (t + bt), in place
#pragma unroll
        for (int mt = 0; mt < 4; ++mt)
#pragma unroll
            for (int nt = 0; nt < 8; ++nt) {
                int m = wm * 64 + mt * 16 + r;
                int ct = (wn - 2) * 64 + nt * 8 + cq;
                float bg0 = bg[ct], bg1 = bg[ct + 1];
                float bt0 = bt[ct], bt1 = bt[ct + 1];
                float* p = sOut + m * OUTROW + ct;
                float g0 = p[0], g1 = p[1];
                float g2 = p[8 * OUTROW], g3 = p[8 * OUTROW + 1];
                p[0] = (acc[mt][nt][0] + bt0) / (1.0f + __expf(-(g0 + bg0)));
                p[1] = (acc[mt][nt][1] + bt1) / (1.0f + __expf(-(g1 + bg1)));
                p[8 * OUTROW]     = (acc[mt][nt][2] + bt0) / (1.0f + __expf(-(g2 + bg0)));
                p[8 * OUTROW + 1] = (acc[mt][nt][3] + bt1) / (1.0f + __expf(-(g3 + bg1)));
            }
    }
    __syncthreads();

    // sorted-id run-length segment sum: 2 threads per channel, 64 nodes each
    {
        const int c = tid & 127;
        const int n0 = (tid >> 7) * 64;
        float run = 0.0f;
        int cur = s_gid[n0];
        for (int n = n0; n < n0 + 64; ++n) {
            int g = s_gid[n];
            if (g != cur) {
                atomicAdd(&g_readout[(size_t)cur * Cc + c], run);
                run = 0.0f; cur = g;
            }
            run += sOut[n * OUTROW + c];
        }
        atomicAdd(&g_readout[(size_t)cur * Cc + c], run);
    }
}

// ---------------- kernel: per-column BN stats -> scale/shift ----------------
__global__ __launch_bounds__(256)
void stats_kernel(const float* __restrict__ aux,
                  const float* __restrict__ gamma, const float* __restrict__ beta) {
    const int j = blockIdx.x;
    const int tid = threadIdx.x;
    float s = 0.0f, sq = 0.0f;
    for (int g = tid; g < NGg; g += 256) {
        float v = (j < Cc) ? g_readout[(size_t)g * Cc + j]
                           : aux[(size_t)g * Aa + (j - Cc)];
        s += v; sq += v * v;
    }
#pragma unroll
    for (int o = 16; o; o >>= 1) {
        s  += __shfl_xor_sync(0xffffffffu, s,  o);
        sq += __shfl_xor_sync(0xffffffffu, sq, o);
    }
    __shared__ float ws[8], wq[8];
    if ((tid & 31) == 0) { ws[tid >> 5] = s; wq[tid >> 5] = sq; }
    __syncthreads();
    if (tid == 0) {
        float S = 0.0f, Q = 0.0f;
#pragma unroll
        for (int i = 0; i < 8; i++) { S += ws[i]; Q += wq[i]; }
        float mean = S * (1.0f / NGg);
        float var  = Q * (1.0f / NGg) - mean * mean;
        float sc = gamma[j] * rsqrtf(var + BN_EPS);
        g_scale[j] = sc;
        g_shift[j] = beta[j] - mean * sc;
    }
}

// ---------------- kernel: hidden = relu(norm @ W1 + b1) ----------------
__global__ __launch_bounds__(256)
void mlp1_kernel(const float* __restrict__ aux,
                 const float* __restrict__ W1, const float* __restrict__ b1) {
    __shared__ float sA[64][33];
    __shared__ float sB[32][128];
    const int tid = threadIdx.x;
    const int tm = tid >> 4, tc = tid & 15;
    const int c0 = tc * 8;
    const int rowBase = blockIdx.x * 64;
    const int colBase = blockIdx.y * 128;

    unsigned long long acc[4][4];
#pragma unroll
    for (int i = 0; i < 4; i++)
#pragma unroll
        for (int j = 0; j < 4; j++) acc[i][j] = 0ULL;

    for (int chunk = 0; chunk < 5; ++chunk) {       // K = 160
        const int k0 = chunk * 32;
        __syncthreads();
#pragma unroll
        for (int it = 0; it < 2; ++it) {
            int f = tid + it * 256;
            int n = f >> 3, q = f & 7;
            int j = k0 + 4 * q;
            float4 v;
            if (j < Cc) v = *(const float4*)(g_readout + (size_t)(rowBase + n) * Cc + j);
            else        v = *(const float4*)(aux + (size_t)(rowBase + n) * Aa + (j - Cc));
            float4 sc = *(const float4*)(g_scale + j);
            float4 sh = *(const float4*)(g_shift + j);
            sA[n][4 * q + 0] = fmaf(v.x, sc.x, sh.x);
            sA[n][4 * q + 1] = fmaf(v.y, sc.y, sh.y);
            sA[n][4 * q + 2] = fmaf(v.z, sc.z, sh.z);
            sA[n][4 * q + 3] = fmaf(v.w, sc.w, sh.w);
        }
#pragma unroll
        for (int it = 0; it < 4; ++it) {
            int f = tid + it * 256;
            int k = f >> 5, c4 = (f & 31) * 4;
            *(float4*)&sB[k][c4] = *(const float4*)(W1 + (size_t)(k0 + k) * Gg + colBase + c4);
        }
        __syncthreads();
#pragma unroll 4
        for (int k = 0; k < 32; ++k) {
            unsigned long long av[4];
#pragma unroll
            for (int i = 0; i < 4; i++) { float a = sA[tm * 4 + i][k]; av[i] = pack2(a, a); }
            ulonglong2 wA = *(const ulonglong2*)&sB[k][c0];
            ulonglong2 wB = *(const ulonglong2*)&sB[k][c0 + 4];
#pragma unroll
            for (int i = 0; i < 4; i++) {
                acc[i][0] = fma2(av[i], wA.x, acc[i][0]);
                acc[i][1] = fma2(av[i], wA.y, acc[i][1]);
                acc[i][2] = fma2(av[i], wB.x, acc[i][2]);
                acc[i][3] = fma2(av[i], wB.y, acc[i][3]);
            }
        }
    }
    float bv[8];
#pragma unroll
    for (int j = 0; j < 8; j++) bv[j] = b1[colBase + c0 + j];
#pragma unroll
    for (int i = 0; i < 4; i++) {
        int r = rowBase + tm * 4 + i;
#pragma unroll
        for (int j = 0; j < 4; j++) {
            float lo, hi; unpack2(acc[i][j], lo, hi);
            lo = fmaxf(lo + bv[2 * j], 0.0f);
            hi = fmaxf(hi + bv[2 * j + 1], 0.0f);
            g_hidden[(size_t)r * Gg + colBase + c0 + 2 * j]     = lo;
            g_hidden[(size_t)r * Gg + colBase + c0 + 2 * j + 1] = hi;
        }
    }
}

// ---------------- kernel: logits = hidden @ W2 + b2 ----------------
__global__ __launch_bounds__(256)
void mlp2_kernel(const float* __restrict__ W2, const float* __restrict__ b2,
                 float* __restrict__ out) {
    __shared__ float sA[16][65];
    __shared__ float sB[64][128];
    const int tid = threadIdx.x;
    const int tm = tid >> 4, tc = tid & 15;
    const int c0 = tc * 8;
    const int rowBase = blockIdx.x * 16;

    unsigned long long acc[4] = {0ULL, 0ULL, 0ULL, 0ULL};
    for (int chunk = 0; chunk < 8; ++chunk) {       // K = 512
        const int k0 = chunk * 64;
        __syncthreads();
        {
            int n = tid >> 4, q = tid & 15;
            float4 v = *(const float4*)(g_hidden + (size_t)(rowBase + n) * Gg + k0 + 4 * q);
            sA[n][4 * q + 0] = v.x; sA[n][4 * q + 1] = v.y;
            sA[n][4 * q + 2] = v.z; sA[n][4 * q + 3] = v.w;
        }
#pragma unroll
        for (int it = 0; it < 8; ++it) {
            int f = tid + it * 256;
            int k = f >> 5, c4 = (f & 31) * 4;
            *(float4*)&sB[k][c4] = *(const float4*)(W2 + (size_t)(k0 + k) * Cc + c4);
        }
        __syncthreads();
#pragma unroll 8
        for (int k = 0; k < 64; ++k) {
            float a = sA[tm][k];
            unsigned long long av = pack2(a, a);
            ulonglong2 wA = *(const ulonglong2*)&sB[k][c0];
            ulonglong2 wB = *(const ulonglong2*)&sB[k][c0 + 4];
            acc[0] = fma2(av, wA.x, acc[0]);
            acc[1] = fma2(av, wA.y, acc[1]);
            acc[2] = fma2(av, wB.x, acc[2]);
            acc[3] = fma2(av, wB.y, acc[3]);
        }
    }
#pragma unroll
    for (int j = 0; j < 4; j++) {
        float lo, hi; unpack2(acc[j], lo, hi);
        int r = rowBase + tm;
        out[(size_t)r * Cc + c0 + 2 * j]     = lo + b2[c0 + 2 * j];
        out[(size_t)r * Cc + c0 + 2 * j + 1] = hi + b2[c0 + 2 * j + 1];
    }
}

// ---------------- launch ----------------
extern "C" void kernel_launch(void* const* d_in, const int* in_sizes, int n_in,
                              void* d_out, int out_size) {
    (void)in_sizes; (void)out_size;
    const float* xinit = (const float*)d_in[0];
    const float* xfin  = (const float*)d_in[1];
    const float* aux   = (const float*)d_in[2];
    const int*   gid   = (const int*)d_in[3];
    const int wb = (n_in >= 15) ? 5 : 4;
    const float* Wg    = (const float*)d_in[wb + 0];
    const float* bg    = (const float*)d_in[wb + 1];
    const float* Wt    = (const float*)d_in[wb + 2];
    const float* bt    = (const float*)d_in[wb + 3];
    const float* gamma = (const float*)d_in[wb + 4];
    const float* beta  = (const float*)d_in[wb + 5];
    const float* W1    = (const float*)d_in[wb + 6];
    const float* b1    = (const float*)d_in[wb + 7];
    const float* W2    = (const float*)d_in[wb + 8];
    const float* b2    = (const float*)d_in[wb + 9];

    cudaFuncSetAttribute(node_kernel, cudaFuncAttributeMaxDynamicSharedMemorySize, SMEM_DYN);

    prep_kernel<<<(Nt * Kt) / 256, 256>>>(Wg, Wt);   // also zeroes g_readout
    node_kernel<<<Nn / Mt, NTHR, SMEM_DYN>>>(xinit, xfin, gid, bg, bt);
    stats_kernel<<<CpA, 256>>>(aux, gamma, beta);
    mlp1_kernel<<<dim3(NGg / 64, Gg / 128), 256>>>(aux, W1, b1);
    mlp2_kernel<<<NGg / 16, 256>>>(W2, b2, (float*)d_out);
}

// round 8
// speedup vs baseline: 1.1483x; 1.1483x over previous
#include <cuda_runtime.h>
#include <cuda_bf16.h>
#include <cuda_fp16.h>
#include <cstdint>

// Problem constants
#define Nn   400000
#define Hh   256
#define Cc   128
#define Aa   32
#define Gg   512
#define NGg  1024
#define CpA  (Cc + Aa)          // 160
#define BN_EPS 1e-5f

#define Kt   512                // concat K: [init | fin]
#define Nt   256                // outputs: [gate(128) | t(128)]
#define Mt   128                // nodes per block
#define KC   128                // K chunk (doubled: 4 iterations, half the barriers)
#define NCH  4                  // number of K chunks
#define AROW (KC + 8)           // padded smem row, elems (136)

// ---------------- scratch (no allocations allowed) ----------------
__device__ float g_readout[NGg * Cc];            // segment sums  [1024,128]
__device__ float g_scale[CpA];
__device__ float g_shift[CpA];
__device__ float g_hidden[NGg * Gg];
__device__ __align__(16) __half g_Bh[Nt * Kt];   // combined weights [n][k], fp16

// ---------------- PTX helpers ----------------
__device__ __forceinline__ uint32_t smem_u32(const void* p) {
    uint32_t a;
    asm("{ .reg .u64 t; cvta.to.shared.u64 t, %1; cvt.u32.u64 %0, t; }" : "=r"(a) : "l"(p));
    return a;
}
#define LDSM4(r, addr)                                                        \
    asm volatile("ldmatrix.sync.aligned.m8n8.x4.shared.b16 {%0,%1,%2,%3}, [%4];" \
        : "=r"((r)[0]), "=r"((r)[1]), "=r"((r)[2]), "=r"((r)[3]) : "r"(addr))

#define MMA(d, a, b0, b1)                                                     \
    asm volatile("mma.sync.aligned.m16n8k16.row.col.f32.f16.f16.f32 "         \
        "{%0,%1,%2,%3},{%4,%5,%6,%7},{%8,%9},{%0,%1,%2,%3};"                  \
        : "+f"((d)[0]), "+f"((d)[1]), "+f"((d)[2]), "+f"((d)[3])              \
        : "r"((a)[0]), "r"((a)[1]), "r"((a)[2]), "r"((a)[3]), "r"(b0), "r"(b1))

#define CP16(dst, src)                                                        \
    asm volatile("cp.async.cg.shared.global [%0], [%1], 16;" :: "r"(dst), "l"(src) : "memory")
#define CP_COMMIT() asm volatile("cp.async.commit_group;" ::: "memory")
#define CP_WAIT0()  asm volatile("cp.async.wait_group 0;" ::: "memory")

// ---------------- packed f32x2 helpers (MLP tail kernels) ----------------
__device__ __forceinline__ unsigned long long pack2(float lo, float hi) {
    unsigned long long r;
    asm("mov.b64 %0, {%1, %2};" : "=l"(r) : "f"(lo), "f"(hi));
    return r;
}
__device__ __forceinline__ void unpack2(unsigned long long v, float& lo, float& hi) {
    asm("mov.b64 {%0, %1}, %2;" : "=f"(lo), "=f"(hi) : "l"(v));
}
__device__ __forceinline__ unsigned long long fma2(unsigned long long a,
                                                   unsigned long long b,
                                                   unsigned long long c) {
    unsigned long long d;
    asm("fma.rn.f32x2 %0, %1, %2, %3;" : "=l"(d) : "l"(a), "l"(b), "l"(c));
    return d;
}

// ---------------- kernel: build combined fp16 weights + zero readout ----------------
// B[n][k]: n<128 -> Wg[k][n]; n>=128 -> (k>=256 ? Wt[k-256][n-128] : 0)
__global__ void prep_kernel(const float* __restrict__ Wg, const float* __restrict__ Wt) {
    int idx = blockIdx.x * 256 + threadIdx.x;     // 0 .. 131071
    int n = idx >> 9, k = idx & 511;
    float w;
    if (n < 128)          w = Wg[(size_t)k * Cc + n];
    else if (k >= 256)    w = Wt[(size_t)(k - 256) * Cc + (n - 128)];
    else                  w = 0.0f;
    g_Bh[idx] = __float2half_rn(w);
    g_readout[idx] = 0.0f;
}

// ---------------- node kernel: HMMA GEMM + gate + segment-sum ----------------
// dynamic smem, 2 stages of:
//   A [128][136] fp16 (34816B) | B [256][136] fp16 (69632B)  = 104448B/stage
#define OFF_B     34816
#define STG       104448
#define SMEM_DYN  (2 * STG)      // 208896
#define OUTROW    132            // fp32 out tile row stride (elems)

__device__ __forceinline__ void ldgA(const float* __restrict__ X, int nodeBase,
                                     int kloc, int tid, float4* aR) {
#pragma unroll
    for (int it = 0; it < 8; ++it) {
        int f = tid + it * 512;
        int m = f >> 5, q = f & 31;          // 32 float4 per 128-col row
        aR[it] = *(const float4*)(X + (size_t)(nodeBase + m) * Hh + kloc + 4 * q);
    }
}

__device__ __forceinline__ void stsA(char* stage, int tid, const float4* aR) {
#pragma unroll
    for (int it = 0; it < 8; ++it) {
        int f = tid + it * 512;
        int m = f >> 5, q = f & 31;
        float4 v = aR[it];
        __half2 h0 = __floats2half2_rn(v.x, v.y);
        __half2 h1 = __floats2half2_rn(v.z, v.w);
        uint32_t off = m * (AROW * 2) + q * 8;
        uint2 H; H.x = *(uint32_t*)&h0; H.y = *(uint32_t*)&h1;
        *(uint2*)(stage + off) = H;
    }
}

// copy B rows [0, nrows) for one 128-wide K chunk; nrows is 128 or 256
__device__ __forceinline__ void cpB(uint32_t stB, int kbytes, int tid, int nrows) {
    const int iters = nrows >> 5;                // 4 or 8 (16 chunks of 16B per row)
    for (int it = 0; it < iters; ++it) {
        int f = tid + it * 512;
        int n = f >> 4, q = f & 15;
        uint32_t dst = n * (AROW * 2) + q * 16;
        CP16(stB + dst, (const char*)g_Bh + (size_t)n * (Kt * 2) + kbytes + q * 16);
    }
    CP_COMMIT();
}

__global__ __launch_bounds__(512, 1)
void node_kernel(const float* __restrict__ xinit, const float* __restrict__ xfin,
                 const int* __restrict__ gids,
                 const float* __restrict__ bg, const float* __restrict__ bt) {
    extern __shared__ char smem[];
    __shared__ int s_gid[Mt];
    const uint32_t sbase = smem_u32(smem);
    const int tid = threadIdx.x;
    const int wid = tid >> 5;
    const int l = tid & 31;
    const int wm = wid & 3;          // 0..3 -> 32 rows each
    const int wn = wid >> 2;         // 0..3 -> 64 cols each
    const int nodeBase = blockIdx.x * Mt;

    if (tid < Mt) s_gid[tid] = gids[nodeBase + tid];

    // ldmatrix per-thread offsets (bytes)
    const uint32_t aOff = ((wm * 32 + (l & 15)) * AROW + ((l >> 4) * 8)) * 2;
    const uint32_t bOff = ((wn * 64 + ((l >> 4) & 1) * 8 + (l & 7)) * AROW +
                           ((l >> 3) & 1) * 8) * 2 + OFF_B;

    float acc[2][8][4];
#pragma unroll
    for (int i = 0; i < 2; i++)
#pragma unroll
        for (int j = 0; j < 8; j++)
#pragma unroll
            for (int p = 0; p < 4; p++) acc[i][j][p] = 0.0f;

    float4 rA[8];

    // prologue: chunk 0 staged (init half, gate-only B rows)
    ldgA(xinit, nodeBase, 0, tid, rA);
    cpB(sbase + OFF_B, 0, tid, 128);
    stsA(smem, tid, rA);
    CP_WAIT0();
    __syncthreads();

    for (int j = 0; j < NCH; ++j) {
        const uint32_t stg = sbase + (uint32_t)(j & 1) * STG;
        // prefetch chunk j+1 into the other stage
        if (j + 1 < NCH) {
            const int c = j + 1;
            cpB(sbase + (uint32_t)(c & 1) * STG + OFF_B, c * (KC * 2), tid,
                (c < 2) ? 128 : 256);
            const float* X = (c < 2) ? xinit : xfin;
            ldgA(X, nodeBase, (c & 1) * KC, tid, rA);
        }

        // chunks 0-1 hit the init half, where all t-columns of B are zero:
        // t warps (wn >= 2) skip their LDSM+MMA block entirely.
        if (j >= 2 || wn < 2) {
#pragma unroll
            for (int ks = 0; ks < 8; ++ks) {
                const uint32_t aA = stg + aOff + ks * 32;
                uint32_t ah0[4], ah1[4];
                LDSM4(ah0, aA);
                LDSM4(ah1, aA + 16 * AROW * 2);
#pragma unroll
                for (int np = 0; np < 4; ++np) {
                    const uint32_t bA = stg + bOff + np * (16 * AROW * 2) + ks * 32;
                    uint32_t bh[4];
                    LDSM4(bh, bA);
                    MMA(acc[0][2 * np],     ah0, bh[0], bh[1]);
                    MMA(acc[0][2 * np + 1], ah0, bh[2], bh[3]);
                    MMA(acc[1][2 * np],     ah1, bh[0], bh[1]);
                    MMA(acc[1][2 * np + 1], ah1, bh[2], bh[3]);
                }
            }
        }

        // STS chunk j+1 (LDG'd at top of this iteration -> full MMA block of slack)
        if (j + 1 < NCH) {
            stsA(smem + ((j + 1) & 1) * STG, tid, rA);
            CP_WAIT0();
        }
        __syncthreads();
    }

    // ---- epilogue ----
    float* sOut = (float*)smem;          // [128][OUTROW] fp32, aliases stages
    const int r = l >> 2;
    const int cq = (l & 3) * 2;

    if (wn < 2) {        // gate warps: store raw gate logits
#pragma unroll
        for (int mt = 0; mt < 2; ++mt)
#pragma unroll
            for (int nt = 0; nt < 8; ++nt) {
                int m = wm * 32 + mt * 16 + r;
                int c = wn * 64 + nt * 8 + cq;
                float* p = sOut + m * OUTROW + c;
                p[0] = acc[mt][nt][0];
                p[1] = acc[mt][nt][1];
                p[8 * OUTROW] = acc[mt][nt][2];
                p[8 * OUTROW + 1] = acc[mt][nt][3];
            }
    }
    __syncthreads();
    if (wn >= 2) {       // t warps: out = sigmoid(g + bg) * (t + bt), in place
#pragma unroll
        for (int mt = 0; mt < 2; ++mt)
#pragma unroll
            for (int nt = 0; nt < 8; ++nt) {
                int m = wm * 32 + mt * 16 + r;
                int ct = (wn - 2) * 64 + nt * 8 + cq;
                float bg0 = bg[ct], bg1 = bg[ct + 1];
                float bt0 = bt[ct], bt1 = bt[ct + 1];
                float* p = sOut + m * OUTROW + ct;
                float g0 = p[0], g1 = p[1];
                float g2 = p[8 * OUTROW], g3 = p[8 * OUTROW + 1];
                p[0] = (acc[mt][nt][0] + bt0) / (1.0f + __expf(-(g0 + bg0)));
                p[1] = (acc[mt][nt][1] + bt1) / (1.0f + __expf(-(g1 + bg1)));
                p[8 * OUTROW]     = (acc[mt][nt][2] + bt0) / (1.0f + __expf(-(g2 + bg0)));
                p[8 * OUTROW + 1] = (acc[mt][nt][3] + bt1) / (1.0f + __expf(-(g3 + bg1)));
            }
    }
    __syncthreads();

    // sorted-id run-length segment sum: 4 threads per channel, 32 nodes each
    {
        const int c = tid & 127;
        const int n0 = (tid >> 7) * 32;
        float run = 0.0f;
        int cur = s_gid[n0];
        for (int n = n0; n < n0 + 32; ++n) {
            int g = s_gid[n];
            if (g != cur) {
                atomicAdd(&g_readout[(size_t)cur * Cc + c], run);
                run = 0.0f; cur = g;
            }
            run += sOut[n * OUTROW + c];
        }
        atomicAdd(&g_readout[(size_t)cur * Cc + c], run);
    }
}

// ---------------- kernel: per-column BN stats -> scale/shift ----------------
__global__ __launch_bounds__(256)
void stats_kernel(const float* __restrict__ aux,
                  const float* __restrict__ gamma, const float* __restrict__ beta) {
    const int j = blockIdx.x;
    const int tid = threadIdx.x;
    float s = 0.0f, sq = 0.0f;
    for (int g = tid; g < NGg; g += 256) {
        float v = (j < Cc) ? g_readout[(size_t)g * Cc + j]
                           : aux[(size_t)g * Aa + (j - Cc)];
        s += v; sq += v * v;
    }
#pragma unroll
    for (int o = 16; o; o >>= 1) {
        s  += __shfl_xor_sync(0xffffffffu, s,  o);
        sq += __shfl_xor_sync(0xffffffffu, sq, o);
    }
    __shared__ float ws[8], wq[8];
    if ((tid & 31) == 0) { ws[tid >> 5] = s; wq[tid >> 5] = sq; }
    __syncthreads();
    if (tid == 0) {
        float S = 0.0f, Q = 0.0f;
#pragma unroll
        for (int i = 0; i < 8; i++) { S += ws[i]; Q += wq[i]; }
        float mean = S * (1.0f / NGg);
        float var  = Q * (1.0f / NGg) - mean * mean;
        float sc = gamma[j] * rsqrtf(var + BN_EPS);
        g_scale[j] = sc;
        g_shift[j] = beta[j] - mean * sc;
    }
}

// ---------------- kernel: hidden = relu(norm @ W1 + b1) ----------------
__global__ __launch_bounds__(256)
void mlp1_kernel(const float* __restrict__ aux,
                 const float* __restrict__ W1, const float* __restrict__ b1) {
    __shared__ float sA[64][33];
    __shared__ float sB[32][128];
    const int tid = threadIdx.x;
    const int tm = tid >> 4, tc = tid & 15;
    const int c0 = tc * 8;
    const int rowBase = blockIdx.x * 64;
    const int colBase = blockIdx.y * 128;

    unsigned long long acc[4][4];
#pragma unroll
    for (int i = 0; i < 4; i++)
#pragma unroll
        for (int j = 0; j < 4; j++) acc[i][j] = 0ULL;

    for (int chunk = 0; chunk < 5; ++chunk) {       // K = 160
        const int k0 = chunk * 32;
        __syncthreads();
#pragma unroll
        for (int it = 0; it < 2; ++it) {
            int f = tid + it * 256;
            int n = f >> 3, q = f & 7;
            int j = k0 + 4 * q;
            float4 v;
            if (j < Cc) v = *(const float4*)(g_readout + (size_t)(rowBase + n) * Cc + j);
            else        v = *(const float4*)(aux + (size_t)(rowBase + n) * Aa + (j - Cc));
            float4 sc = *(const float4*)(g_scale + j);
            float4 sh = *(const float4*)(g_shift + j);
            sA[n][4 * q + 0] = fmaf(v.x, sc.x, sh.x);
            sA[n][4 * q + 1] = fmaf(v.y, sc.y, sh.y);
            sA[n][4 * q + 2] = fmaf(v.z, sc.z, sh.z);
            sA[n][4 * q + 3] = fmaf(v.w, sc.w, sh.w);
        }
#pragma unroll
        for (int it = 0; it < 4; ++it) {
            int f = tid + it * 256;
            int k = f >> 5, c4 = (f & 31) * 4;
            *(float4*)&sB[k][c4] = *(const float4*)(W1 + (size_t)(k0 + k) * Gg + colBase + c4);
        }
        __syncthreads();
#pragma unroll 4
        for (int k = 0; k < 32; ++k) {
            unsigned long long av[4];
#pragma unroll
            for (int i = 0; i < 4; i++) { float a = sA[tm * 4 + i][k]; av[i] = pack2(a, a); }
            ulonglong2 wA = *(const ulonglong2*)&sB[k][c0];
            ulonglong2 wB = *(const ulonglong2*)&sB[k][c0 + 4];
#pragma unroll
            for (int i = 0; i < 4; i++) {
                acc[i][0] = fma2(av[i], wA.x, acc[i][0]);
                acc[i][1] = fma2(av[i], wA.y, acc[i][1]);
                acc[i][2] = fma2(av[i], wB.x, acc[i][2]);
                acc[i][3] = fma2(av[i], wB.y, acc[i][3]);
            }
        }
    }
    float bv[8];
#pragma unroll
    for (int j = 0; j < 8; j++) bv[j] = b1[colBase + c0 + j];
#pragma unroll
    for (int i = 0; i < 4; i++) {
        int r = rowBase + tm * 4 + i;
#pragma unroll
        for (int j = 0; j < 4; j++) {
            float lo, hi; unpack2(acc[i][j], lo, hi);
            lo = fmaxf(lo + bv[2 * j], 0.0f);
            hi = fmaxf(hi + bv[2 * j + 1], 0.0f);
            g_hidden[(size_t)r * Gg + colBase + c0 + 2 * j]     = lo;
            g_hidden[(size_t)r * Gg + colBase + c0 + 2 * j + 1] = hi;
        }
    }
}

// ---------------- kernel: logits = hidden @ W2 + b2 ----------------
__global__ __launch_bounds__(256)
void mlp2_kernel(const float* __restrict__ W2, const float* __restrict__ b2,
                 float* __restrict__ out) {
    __shared__ float sA[16][65];
    __shared__ float sB[64][128];
    const int tid = threadIdx.x;
    const int tm = tid >> 4, tc = tid & 15;
    const int c0 = tc * 8;
    const int rowBase = blockIdx.x * 16;

    unsigned long long acc[4] = {0ULL, 0ULL, 0ULL, 0ULL};
    for (int chunk = 0; chunk < 8; ++chunk) {       // K = 512
        const int k0 = chunk * 64;
        __syncthreads();
        {
            int n = tid >> 4, q = tid & 15;
            float4 v = *(const float4*)(g_hidden + (size_t)(rowBase + n) * Gg + k0 + 4 * q);
            sA[n][4 * q + 0] = v.x; sA[n][4 * q + 1] = v.y;
            sA[n][4 * q + 2] = v.z; sA[n][4 * q + 3] = v.w;
        }
#pragma unroll
        for (int it = 0; it < 8; ++it) {
            int f = tid + it * 256;
            int k = f >> 5, c4 = (f & 31) * 4;
            *(float4*)&sB[k][c4] = *(const float4*)(W2 + (size_t)(k0 + k) * Cc + c4);
        }
        __syncthreads();
#pragma unroll 8
        for (int k = 0; k < 64; ++k) {
            float a = sA[tm][k];
            unsigned long long av = pack2(a, a);
            ulonglong2 wA = *(const ulonglong2*)&sB[k][c0];
            ulonglong2 wB = *(const ulonglong2*)&sB[k][c0 + 4];
            acc[0] = fma2(av, wA.x, acc[0]);
            acc[1] = fma2(av, wA.y, acc[1]);
            acc[2] = fma2(av, wB.x, acc[2]);
            acc[3] = fma2(av, wB.y, acc[3]);
        }
    }
#pragma unroll
    for (int j = 0; j < 4; j++) {
        float lo, hi; unpack2(acc[j], lo, hi);
        int r = rowBase + tm;
        out[(size_t)r * Cc + c0 + 2 * j]     = lo + b2[c0 + 2 * j];
        out[(size_t)r * Cc + c0 + 2 * j + 1] = hi + b2[c0 + 2 * j + 1];
    }
}

// ---------------- launch ----------------
extern "C" void kernel_launch(void* const* d_in, const int* in_sizes, int n_in,
                              void* d_out, int out_size) {
    (void)in_sizes; (void)out_size;
    const float* xinit = (const float*)d_in[0];
    const float* xfin  = (const float*)d_in[1];
    const float* aux   = (const float*)d_in[2];
    const int*   gid   = (const int*)d_in[3];
    const int wb = (n_in >= 15) ? 5 : 4;
    const float* Wg    = (const float*)d_in[wb + 0];
    const float* bg    = (const float*)d_in[wb + 1];
    const float* Wt    = (const float*)d_in[wb + 2];
    const float* bt    = (const float*)d_in[wb + 3];
    const float* gamma = (const float*)d_in[wb + 4];
    const float* beta  = (const float*)d_in[wb + 5];
    const float* W1    = (const float*)d_in[wb + 6];
    const float* b1    = (const float*)d_in[wb + 7];
    const float* W2    = (const float*)d_in[wb + 8];
    const float* b2    = (const float*)d_in[wb + 9];

    cudaFuncSetAttribute(node_kernel, cudaFuncAttributeMaxDynamicSharedMemorySize, SMEM_DYN);

    prep_kernel<<<(Nt * Kt) / 256, 256>>>(Wg, Wt);   // also zeroes g_readout
    node_kernel<<<Nn / Mt, 512, SMEM_DYN>>>(xinit, xfin, gid, bg, bt);
    stats_kernel<<<CpA, 256>>>(aux, gamma, beta);
    mlp1_kernel<<<dim3(NGg / 64, Gg / 128), 256>>>(aux, W1, b1);
    mlp2_kernel<<<NGg / 16, 256>>>(W2, b2, (float*)d_out);
}

// round 9
// speedup vs baseline: 1.3888x; 1.2094x over previous
#include <cuda_runtime.h>
#include <cuda_bf16.h>
#include <cuda_fp16.h>
#include <cstdint>

// Problem constants
#define Nn   400000
#define Hh   256
#define Cc   128
#define Aa   32
#define Gg   512
#define NGg  1024
#define CpA  (Cc + Aa)          // 160
#define BN_EPS 1e-5f

#define Kt   512                // concat K: [init | fin]
#define Nt   256                // outputs: [gate(128) | t(128)]
#define Mt   64                 // nodes per block (halved -> 2 CTAs/SM)
#define KC   64                 // K chunk
#define AROW (KC + 8)           // padded smem row, elems (72)
#define NTHR 256                // 8 warps: 2 row-groups x 4 col-groups (32x64 tiles)

// ---------------- scratch (no allocations allowed) ----------------
__device__ float g_readout[NGg * Cc];            // segment sums  [1024,128]
__device__ float g_scale[CpA];
__device__ float g_shift[CpA];
__device__ float g_hidden[NGg * Gg];
__device__ __align__(16) __half g_Bh[Nt * Kt];   // combined weights [n][k], fp16

// ---------------- PTX helpers ----------------
__device__ __forceinline__ uint32_t smem_u32(const void* p) {
    uint32_t a;
    asm("{ .reg .u64 t; cvta.to.shared.u64 t, %1; cvt.u32.u64 %0, t; }" : "=r"(a) : "l"(p));
    return a;
}
#define LDSM4(r, addr)                                                        \
    asm volatile("ldmatrix.sync.aligned.m8n8.x4.shared.b16 {%0,%1,%2,%3}, [%4];" \
        : "=r"((r)[0]), "=r"((r)[1]), "=r"((r)[2]), "=r"((r)[3]) : "r"(addr))

#define MMA(d, a, b0, b1)                                                     \
    asm volatile("mma.sync.aligned.m16n8k16.row.col.f32.f16.f16.f32 "         \
        "{%0,%1,%2,%3},{%4,%5,%6,%7},{%8,%9},{%0,%1,%2,%3};"                  \
        : "+f"((d)[0]), "+f"((d)[1]), "+f"((d)[2]), "+f"((d)[3])              \
        : "r"((a)[0]), "r"((a)[1]), "r"((a)[2]), "r"((a)[3]), "r"(b0), "r"(b1))

#define CP16(dst, src)                                                        \
    asm volatile("cp.async.cg.shared.global [%0], [%1], 16;" :: "r"(dst), "l"(src) : "memory")
#define CP_COMMIT() asm volatile("cp.async.commit_group;" ::: "memory")
#define CP_WAIT0()  asm volatile("cp.async.wait_group 0;" ::: "memory")

// ---------------- packed f32x2 helpers (MLP tail kernels) ----------------
__device__ __forceinline__ unsigned long long pack2(float lo, float hi) {
    unsigned long long r;
    asm("mov.b64 %0, {%1, %2};" : "=l"(r) : "f"(lo), "f"(hi));
    return r;
}
__device__ __forceinline__ void unpack2(unsigned long long v, float& lo, float& hi) {
    asm("mov.b64 {%0, %1}, %2;" : "=f"(lo), "=f"(hi) : "l"(v));
}
__device__ __forceinline__ unsigned long long fma2(unsigned long long a,
                                                   unsigned long long b,
                                                   unsigned long long c) {
    unsigned long long d;
    asm("fma.rn.f32x2 %0, %1, %2, %3;" : "=l"(d) : "l"(a), "l"(b), "l"(c));
    return d;
}

// ---------------- kernel: build combined fp16 weights + zero readout ----------------
// B[n][k]: n<128 -> Wg[k][n]; n>=128 -> (k>=256 ? Wt[k-256][n-128] : 0)
__global__ void prep_kernel(const float* __restrict__ Wg, const float* __restrict__ Wt) {
    int idx = blockIdx.x * 256 + threadIdx.x;     // 0 .. 131071
    int n = idx >> 9, k = idx & 511;
    float w;
    if (n < 128)          w = Wg[(size_t)k * Cc + n];
    else if (k >= 256)    w = Wt[(size_t)(k - 256) * Cc + (n - 128)];
    else                  w = 0.0f;
    g_Bh[idx] = __float2half_rn(w);
    g_readout[idx] = 0.0f;
}

// ---------------- node kernel: HMMA GEMM + gate + segment-sum ----------------
// dynamic smem, 2 stages of:
//   A [64][72] fp16 (9216B) | B [256][72] fp16 (36864B)   = 46080B/stage
// 92160B/CTA -> 2 CTAs per SM
#define OFF_B     9216
#define STG       46080
#define SMEM_DYN  (2 * STG)      // 92160
#define OUTROW    132            // fp32 out tile row stride (elems)

__device__ __forceinline__ void ldgA(const float* __restrict__ X, int nodeBase,
                                     int kloc, int tid, float4* aR) {
#pragma unroll
    for (int it = 0; it < 4; ++it) {
        int f = tid + it * NTHR;
        int m = f >> 4, q = f & 15;
        aR[it] = *(const float4*)(X + (size_t)(nodeBase + m) * Hh + kloc + 4 * q);
    }
}

__device__ __forceinline__ void stsA(char* stage, int tid, const float4* aR) {
#pragma unroll
    for (int it = 0; it < 4; ++it) {
        int f = tid + it * NTHR;
        int m = f >> 4, q = f & 15;
        float4 v = aR[it];
        __half2 h0 = __floats2half2_rn(v.x, v.y);
        __half2 h1 = __floats2half2_rn(v.z, v.w);
        uint32_t off = m * (AROW * 2) + q * 8;
        uint2 H; H.x = *(uint32_t*)&h0; H.y = *(uint32_t*)&h1;
        *(uint2*)(stage + off) = H;
    }
}

// copy B rows [0, nrows) for one K chunk; nrows is 128 (gate-only) or 256
__device__ __forceinline__ void cpB(uint32_t stB, int kbytes, int tid, int nrows) {
    const int iters = nrows >> 5;                // 4 or 8
    for (int it = 0; it < iters; ++it) {
        int f = tid + it * NTHR;
        int n = f >> 3, q = f & 7;
        uint32_t dst = n * (AROW * 2) + q * 16;
        CP16(stB + dst, (const char*)g_Bh + (size_t)n * (Kt * 2) + kbytes + q * 16);
    }
    CP_COMMIT();
}

__global__ __launch_bounds__(NTHR, 2)
void node_kernel(const float* __restrict__ xinit, const float* __restrict__ xfin,
                 const int* __restrict__ gids,
                 const float* __restrict__ bg, const float* __restrict__ bt) {
    extern __shared__ char smem[];
    __shared__ int s_gid[Mt];
    const uint32_t sbase = smem_u32(smem);
    const int tid = threadIdx.x;
    const int wid = tid >> 5;
    const int l = tid & 31;
    const int wm = wid & 1;          // 0..1 -> 32 rows each
    const int wn = wid >> 1;         // 0..3 -> 64 cols each
    const int nodeBase = blockIdx.x * Mt;

    if (tid < Mt) s_gid[tid] = gids[nodeBase + tid];

    // ldmatrix per-thread offsets (bytes)
    const uint32_t aOff = ((wm * 32 + (l & 15)) * AROW + ((l >> 4) * 8)) * 2;
    const uint32_t bOff = ((wn * 64 + ((l >> 4) & 1) * 8 + (l & 7)) * AROW +
                           ((l >> 3) & 1) * 8) * 2 + OFF_B;

    float acc[2][8][4];
#pragma unroll
    for (int i = 0; i < 2; i++)
#pragma unroll
        for (int j = 0; j < 8; j++)
#pragma unroll
            for (int p = 0; p < 4; p++) acc[i][j][p] = 0.0f;

    float4 rA[4];

    // prologue: chunk 0 staged (init half, gate-only B rows)
    ldgA(xinit, nodeBase, 0, tid, rA);
    cpB(sbase + OFF_B, 0, tid, 128);
    stsA(smem, tid, rA);
    CP_WAIT0();
    __syncthreads();

    for (int j = 0; j < 8; ++j) {
        const uint32_t stg = sbase + (uint32_t)(j & 1) * STG;
        // prefetch chunk j+1 into the other stage
        if (j + 1 < 8) {
            const int c = j + 1;
            cpB(sbase + (uint32_t)(c & 1) * STG + OFF_B, c * KC * 2, tid,
                (c < 4) ? 128 : 256);
            const float* X = (c < 4) ? xinit : xfin;
            ldgA(X, nodeBase, (c & 3) * KC, tid, rA);
        }

        // chunks 0-3 hit the init half, where all t-columns of B are zero:
        // t warps (wn >= 2) skip their LDSM+MMA block entirely.
        if (j >= 4 || wn < 2) {
#pragma unroll
            for (int ks = 0; ks < 4; ++ks) {
                const uint32_t aA = stg + aOff + ks * 32;
                uint32_t ah0[4], ah1[4];
                LDSM4(ah0, aA);
                LDSM4(ah1, aA + 16 * AROW * 2);
#pragma unroll
                for (int np = 0; np < 4; ++np) {
                    const uint32_t bA = stg + bOff + np * (16 * AROW * 2) + ks * 32;
                    uint32_t bh[4];
                    LDSM4(bh, bA);
                    MMA(acc[0][2 * np],     ah0, bh[0], bh[1]);
                    MMA(acc[0][2 * np + 1], ah0, bh[2], bh[3]);
                    MMA(acc[1][2 * np],     ah1, bh[0], bh[1]);
                    MMA(acc[1][2 * np + 1], ah1, bh[2], bh[3]);
                }
            }
        }

        // STS chunk j+1 (LDG'd at top of this iteration -> full MMA block of slack)
        if (j + 1 < 8) {
            stsA(smem + ((j + 1) & 1) * STG, tid, rA);
            CP_WAIT0();
        }
        __syncthreads();
    }

    // ---- epilogue ----
    float* sOut = (float*)smem;          // [64][OUTROW] fp32, aliases stages
    const int r = l >> 2;
    const int cq = (l & 3) * 2;

    if (wn < 2) {        // gate warps: store raw gate logits
#pragma unroll
        for (int mt = 0; mt < 2; ++mt)
#pragma unroll
            for (int nt = 0; nt < 8; ++nt) {
                int m = wm * 32 + mt * 16 + r;
                int c = wn * 64 + nt * 8 + cq;
                float* p = sOut + m * OUTROW + c;
                p[0] = acc[mt][nt][0];
                p[1] = acc[mt][nt][1];
                p[8 * OUTROW] = acc[mt][nt][2];
                p[8 * OUTROW + 1] = acc[mt][nt][3];
            }
    }
    __syncthreads();
    if (wn >= 2) {       // t warps: out = sigmoid(g + bg) * (t + bt), in place
#pragma unroll
        for (int mt = 0; mt < 2; ++mt)
#pragma unroll
            for (int nt = 0; nt < 8; ++nt) {
                int m = wm * 32 + mt * 16 + r;
                int ct = (wn - 2) * 64 + nt * 8 + cq;
                float bg0 = bg[ct], bg1 = bg[ct + 1];
                float bt0 = bt[ct], bt1 = bt[ct + 1];
                float* p = sOut + m * OUTROW + ct;
                float g0 = p[0], g1 = p[1];
                float g2 = p[8 * OUTROW], g3 = p[8 * OUTROW + 1];
                p[0] = (acc[mt][nt][0] + bt0) / (1.0f + __expf(-(g0 + bg0)));
                p[1] = (acc[mt][nt][1] + bt1) / (1.0f + __expf(-(g1 + bg1)));
                p[8 * OUTROW]     = (acc[mt][nt][2] + bt0) / (1.0f + __expf(-(g2 + bg0)));
                p[8 * OUTROW + 1] = (acc[mt][nt][3] + bt1) / (1.0f + __expf(-(g3 + bg1)));
            }
    }
    __syncthreads();

    // sorted-id run-length segment sum: 2 threads per channel, 32 nodes each
    {
        const int c = tid & 127;
        const int n0 = (tid >> 7) * 32;
        float run = 0.0f;
        int cur = s_gid[n0];
        for (int n = n0; n < n0 + 32; ++n) {
            int g = s_gid[n];
            if (g != cur) {
                atomicAdd(&g_readout[(size_t)cur * Cc + c], run);
                run = 0.0f; cur = g;
            }
            run += sOut[n * OUTROW + c];
        }
        atomicAdd(&g_readout[(size_t)cur * Cc + c], run);
    }
}

// ---------------- kernel: per-column BN stats -> scale/shift ----------------
__global__ __launch_bounds__(256)
void stats_kernel(const float* __restrict__ aux,
                  const float* __restrict__ gamma, const float* __restrict__ beta) {
    const int j = blockIdx.x;
    const int tid = threadIdx.x;
    float s = 0.0f, sq = 0.0f;
    for (int g = tid; g < NGg; g += 256) {
        float v = (j < Cc) ? g_readout[(size_t)g * Cc + j]
                           : aux[(size_t)g * Aa + (j - Cc)];
        s += v; sq += v * v;
    }
#pragma unroll
    for (int o = 16; o; o >>= 1) {
        s  += __shfl_xor_sync(0xffffffffu, s,  o);
        sq += __shfl_xor_sync(0xffffffffu, sq, o);
    }
    __shared__ float ws[8], wq[8];
    if ((tid & 31) == 0) { ws[tid >> 5] = s; wq[tid >> 5] = sq; }
    __syncthreads();
    if (tid == 0) {
        float S = 0.0f, Q = 0.0f;
#pragma unroll
        for (int i = 0; i < 8; i++) { S += ws[i]; Q += wq[i]; }
        float mean = S * (1.0f / NGg);
        float var  = Q * (1.0f / NGg) - mean * mean;
        float sc = gamma[j] * rsqrtf(var + BN_EPS);
        g_scale[j] = sc;
        g_shift[j] = beta[j] - mean * sc;
    }
}

// ---------------- kernel: hidden = relu(norm @ W1 + b1) ----------------
__global__ __launch_bounds__(256)
void mlp1_kernel(const float* __restrict__ aux,
                 const float* __restrict__ W1, const float* __restrict__ b1) {
    __shared__ float sA[64][33];
    __shared__ float sB[32][128];
    const int tid = threadIdx.x;
    const int tm = tid >> 4, tc = tid & 15;
    const int c0 = tc * 8;
    const int rowBase = blockIdx.x * 64;
    const int colBase = blockIdx.y * 128;

    unsigned long long acc[4][4];
#pragma unroll
    for (int i = 0; i < 4; i++)
#pragma unroll
        for (int j = 0; j < 4; j++) acc[i][j] = 0ULL;

    for (int chunk = 0; chunk < 5; ++chunk) {       // K = 160
        const int k0 = chunk * 32;
        __syncthreads();
#pragma unroll
        for (int it = 0; it < 2; ++it) {
            int f = tid + it * 256;
            int n = f >> 3, q = f & 7;
            int j = k0 + 4 * q;
            float4 v;
            if (j < Cc) v = *(const float4*)(g_readout + (size_t)(rowBase + n) * Cc + j);
            else        v = *(const float4*)(aux + (size_t)(rowBase + n) * Aa + (j - Cc));
            float4 sc = *(const float4*)(g_scale + j);
            float4 sh = *(const float4*)(g_shift + j);
            sA[n][4 * q + 0] = fmaf(v.x, sc.x, sh.x);
            sA[n][4 * q + 1] = fmaf(v.y, sc.y, sh.y);
            sA[n][4 * q + 2] = fmaf(v.z, sc.z, sh.z);
            sA[n][4 * q + 3] = fmaf(v.w, sc.w, sh.w);
        }
#pragma unroll
        for (int it = 0; it < 4; ++it) {
            int f = tid + it * 256;
            int k = f >> 5, c4 = (f & 31) * 4;
            *(float4*)&sB[k][c4] = *(const float4*)(W1 + (size_t)(k0 + k) * Gg + colBase + c4);
        }
        __syncthreads();
#pragma unroll 4
        for (int k = 0; k < 32; ++k) {
            unsigned long long av[4];
#pragma unroll
            for (int i = 0; i < 4; i++) { float a = sA[tm * 4 + i][k]; av[i] = pack2(a, a); }
            ulonglong2 wA = *(const ulonglong2*)&sB[k][c0];
            ulonglong2 wB = *(const ulonglong2*)&sB[k][c0 + 4];
#pragma unroll
            for (int i = 0; i < 4; i++) {
                acc[i][0] = fma2(av[i], wA.x, acc[i][0]);
                acc[i][1] = fma2(av[i], wA.y, acc[i][1]);
                acc[i][2] = fma2(av[i], wB.x, acc[i][2]);
                acc[i][3] = fma2(av[i], wB.y, acc[i][3]);
            }
        }
    }
    float bv[8];
#pragma unroll
    for (int j = 0; j < 8; j++) bv[j] = b1[colBase + c0 + j];
#pragma unroll
    for (int i = 0; i < 4; i++) {
        int r = rowBase + tm * 4 + i;
#pragma unroll
        for (int j = 0; j < 4; j++) {
            float lo, hi; unpack2(acc[i][j], lo, hi);
            lo = fmaxf(lo + bv[2 * j], 0.0f);
            hi = fmaxf(hi + bv[2 * j + 1], 0.0f);
            g_hidden[(size_t)r * Gg + colBase + c0 + 2 * j]     = lo;
            g_hidden[(size_t)r * Gg + colBase + c0 + 2 * j + 1] = hi;
        }
    }
}

// ---------------- kernel: logits = hidden @ W2 + b2 ----------------
__global__ __launch_bounds__(256)
void mlp2_kernel(const float* __restrict__ W2, const float* __restrict__ b2,
                 float* __restrict__ out) {
    __shared__ float sA[16][65];
    __shared__ float sB[64][128];
    const int tid = threadIdx.x;
    const int tm = tid >> 4, tc = tid & 15;
    const int c0 = tc * 8;
    const int rowBase = blockIdx.x * 16;

    unsigned long long acc[4] = {0ULL, 0ULL, 0ULL, 0ULL};
    for (int chunk = 0; chunk < 8; ++chunk) {       // K = 512
        const int k0 = chunk * 64;
        __syncthreads();
        {
            int n = tid >> 4, q = tid & 15;
            float4 v = *(const float4*)(g_hidden + (size_t)(rowBase + n) * Gg + k0 + 4 * q);
            sA[n][4 * q + 0] = v.x; sA[n][4 * q + 1] = v.y;
            sA[n][4 * q + 2] = v.z; sA[n][4 * q + 3] = v.w;
        }
#pragma unroll
        for (int it = 0; it < 8; ++it) {
            int f = tid + it * 256;
            int k = f >> 5, c4 = (f & 31) * 4;
            *(float4*)&sB[k][c4] = *(const float4*)(W2 + (size_t)(k0 + k) * Cc + c4);
        }
        __syncthreads();
#pragma unroll 8
        for (int k = 0; k < 64; ++k) {
            float a = sA[tm][k];
            unsigned long long av = pack2(a, a);
            ulonglong2 wA = *(const ulonglong2*)&sB[k][c0];
            ulonglong2 wB = *(const ulonglong2*)&sB[k][c0 + 4];
            acc[0] = fma2(av, wA.x, acc[0]);
            acc[1] = fma2(av, wA.y, acc[1]);
            acc[2] = fma2(av, wB.x, acc[2]);
            acc[3] = fma2(av, wB.y, acc[3]);
        }
    }
#pragma unroll
    for (int j = 0; j < 4; j++) {
        float lo, hi; unpack2(acc[j], lo, hi);
        int r = rowBase + tm;
        out[(size_t)r * Cc + c0 + 2 * j]     = lo + b2[c0 + 2 * j];
        out[(size_t)r * Cc + c0 + 2 * j + 1] = hi + b2[c0 + 2 * j + 1];
    }
}

// ---------------- launch ----------------
extern "C" void kernel_launch(void* const* d_in, const int* in_sizes, int n_in,
                              void* d_out, int out_size) {
    (void)in_sizes; (void)out_size;
    const float* xinit = (const float*)d_in[0];
    const float* xfin  = (const float*)d_in[1];
    const float* aux   = (const float*)d_in[2];
    const int*   gid   = (const int*)d_in[3];
    const int wb = (n_in >= 15) ? 5 : 4;
    const float* Wg    = (const float*)d_in[wb + 0];
    const float* bg    = (const float*)d_in[wb + 1];
    const float* Wt    = (const float*)d_in[wb + 2];
    const float* bt    = (const float*)d_in[wb + 3];
    const float* gamma = (const float*)d_in[wb + 4];
    const float* beta  = (const float*)d_in[wb + 5];
    const float* W1    = (const float*)d_in[wb + 6];
    const float* b1    = (const float*)d_in[wb + 7];
    const float* W2    = (const float*)d_in[wb + 8];
    const float* b2    = (const float*)d_in[wb + 9];

    cudaFuncSetAttribute(node_kernel, cudaFuncAttributeMaxDynamicSharedMemorySize, SMEM_DYN);

    prep_kernel<<<(Nt * Kt) / 256, 256>>>(Wg, Wt);   // also zeroes g_readout
    node_kernel<<<Nn / Mt, NTHR, SMEM_DYN>>>(xinit, xfin, gid, bg, bt);
    stats_kernel<<<CpA, 256>>>(aux, gamma, beta);
    mlp1_kernel<<<dim3(NGg / 64, Gg / 128), 256>>>(aux, W1, b1);
    mlp2_kernel<<<NGg / 16, 256>>>(W2, b2, (float*)d_out);
}